// round 1
// baseline (speedup 1.0000x reference)
#include <cuda_runtime.h>

// ExponentialGlobalConv: out[b,m,c] = DX * sum_n x[b,n] * exp(-|n-m|*DX / w_c) / (2 w_c)
// Uniform grid => separable exponential kernel => forward+backward IIR scan.
//
// S_f[m] = x[m] + r*S_f[m-1],  S_b[m] = x[m] + r*S_b[m+1],  r = exp(-DX/w)
// out[m] = scale * (S_f[m] + S_b[m] - x[m]),  scale = DX/(2w)
//
// Parallelization: lane = channel (32), warp = 64-wide chunk of m, block = (b, half).
// Chunk-local scans -> inter-chunk carry propagation (hop r^64) -> seeded scans + store.

#define NCH 32
#define NG  2048
#define NB  32
#define DXC 0.08f
#define CL  64            // chunk length
#define NCHUNK (NG / CL)  // 32 chunks
#define NWARP 16          // warps per block
#define NTHREADS (NWARP * 32)

__global__ __launch_bounds__(NTHREADS, 1)
void egc_scan_kernel(const float* __restrict__ x,
                     const float* __restrict__ eta,
                     float* __restrict__ out)
{
    __shared__ float xs[NG];
    __shared__ float ef[NCHUNK][32];
    __shared__ float eb[NCHUNK][32];
    __shared__ float sf[NCHUNK][32];
    __shared__ float sb[NCHUNK][32];

    const int tid  = threadIdx.x;
    const int lane = tid & 31;         // channel
    const int w    = tid >> 5;         // warp id 0..15
    const int b    = blockIdx.x >> 1;  // batch row
    const int half = blockIdx.x & 1;   // which half of m this block writes

    // Per-channel params (lane = channel c)
    const float e     = eta[lane];
    const float sig   = 1.0f / (1.0f + expf(-e));
    const float wid   = 0.1f + 4.9f * sig;          // MIN_XI + (MAX-MIN)*sigmoid
    const float r     = expf(-DXC / wid);
    const float rL    = expf(-DXC * (float)CL / wid); // r^CL via exp (accurate)
    const float scale = DXC / (2.0f * wid);

    // Cooperative load of x[b, :] into shared (vectorized)
    {
        const float4* x4  = reinterpret_cast<const float4*>(x + (size_t)b * NG);
        float4*       xs4 = reinterpret_cast<float4*>(xs);
        #pragma unroll
        for (int i = tid; i < NG / 4; i += NTHREADS) xs4[i] = x4[i];
    }
    __syncthreads();

    // ---- Phase A: chunk-local end sums (seed 0), 2 chunks per warp ----
    #pragma unroll
    for (int rep = 0; rep < NCHUNK / NWARP; rep++) {
        const int j = w + rep * NWARP;
        const float* xc = xs + j * CL;
        float F = 0.0f, B = 0.0f;
        #pragma unroll
        for (int k = 0; k < CL; k++) {
            F = fmaf(r, F, xc[k]);            // forward local scan
            B = fmaf(r, B, xc[CL - 1 - k]);   // backward local scan (independent chain)
        }
        ef[j][lane] = F;
        eb[j][lane] = B;
    }
    __syncthreads();

    // ---- Phase B: inter-chunk carry propagation ----
    if (w == 0) {
        float T = 0.0f;
        #pragma unroll
        for (int j = 0; j < NCHUNK; j++) {
            sf[j][lane] = T;                  // seed for chunk j = S_f at jL-1
            T = fmaf(rL, T, ef[j][lane]);
        }
    } else if (w == 1) {
        float U = 0.0f;
        #pragma unroll
        for (int j = NCHUNK - 1; j >= 0; j--) {
            sb[j][lane] = U;                  // seed for chunk j = S_b at (j+1)L
            U = fmaf(rL, U, eb[j][lane]);
        }
    }
    __syncthreads();

    // ---- Phase C: seeded scans + fused combine/store for this block's half ----
    const int j = half * NWARP + w;
    const float* xc = xs + j * CL;
    float* op = out + ((size_t)b * NG + (size_t)j * CL) * NCH + lane;

    float F = sf[j][lane];
    float Freg[CL];
    #pragma unroll
    for (int k = 0; k < CL; k++) {
        F = fmaf(r, F, xc[k]);
        Freg[k] = F;
    }

    float B = sb[j][lane];
    #pragma unroll
    for (int k = CL - 1; k >= 0; k--) {
        const float xv = xc[k];
        B = fmaf(r, B, xv);
        op[(size_t)k * NCH] = scale * (Freg[k] + B - xv);
    }
}

extern "C" void kernel_launch(void* const* d_in, const int* in_sizes, int n_in,
                              void* d_out, int out_size)
{
    const float* x   = (const float*)d_in[0];  // inputs (32, 2048)
    // d_in[1] = grids (unused: grid is uniform with spacing DX by construction)
    const float* eta = (const float*)d_in[2];  // eta (32,)
    float* out = (float*)d_out;                // (32, 2048, 32) fp32

    egc_scan_kernel<<<NB * 2, NTHREADS>>>(x, eta, out);
}

// round 2
// speedup vs baseline: 1.1204x; 1.1204x over previous
#include <cuda_runtime.h>

// ExponentialGlobalConv: out[b,m,c] = DX * sum_n x[b,n] * exp(-|n-m|*DX / w_c) / (2 w_c)
// Uniform grid => separable exponential kernel => forward+backward IIR scan.
//
// S_f[m] = x[m] + r*S_f[m-1],  S_b[m] = x[m] + r*S_b[m+1],  r = exp(-DX/w)
// out[m] = scale * (S_f[m] + S_b[m] - x[m]),  scale = DX/(2w)
//
// R2 changes vs R1: CL 64->32 (Freg[32] fits in regs, no local spills),
// grid 64->128 CTAs (4 blocks/batch), Phase A interleaves 4 chunks x 2
// directions = 8 independent FMA chains per warp (pay chain latency once).

#define NCH 32
#define NG  2048
#define NB  32
#define DXC 0.08f
#define CL  32            // chunk length
#define NCHUNK (NG / CL)  // 64 chunks
#define NWARP 16          // warps per block
#define NTHREADS (NWARP * 32)
#define CPW (NCHUNK / NWARP)  // 4 chunks per warp in Phase A
#define BLKS_PER_B 4          // each block writes one quarter of the grid dim

__global__ __launch_bounds__(NTHREADS, 1)
void egc_scan_kernel(const float* __restrict__ x,
                     const float* __restrict__ eta,
                     float* __restrict__ out)
{
    __shared__ float xs[NG];
    __shared__ float ef[NCHUNK][32];
    __shared__ float eb[NCHUNK][32];
    __shared__ float sf[NCHUNK][32];
    __shared__ float sb[NCHUNK][32];

    const int tid  = threadIdx.x;
    const int lane = tid & 31;          // channel
    const int w    = tid >> 5;          // warp id 0..15
    const int b    = blockIdx.x >> 2;   // batch row
    const int quar = blockIdx.x & 3;    // which quarter of m this block writes

    // Per-channel params (lane = channel c)
    const float e     = eta[lane];
    const float sig   = 1.0f / (1.0f + expf(-e));
    const float wid   = 0.1f + 4.9f * sig;            // MIN_XI + (MAX-MIN)*sigmoid
    const float r     = expf(-DXC / wid);
    const float rL    = expf(-DXC * (float)CL / wid); // r^CL (accurate via exp)
    const float scale = DXC / (2.0f * wid);

    // Cooperative load of x[b, :] into shared (vectorized)
    {
        const float4* x4  = reinterpret_cast<const float4*>(x + (size_t)b * NG);
        float4*       xs4 = reinterpret_cast<float4*>(xs);
        xs4[tid] = x4[tid];              // 2048/4 = 512 = NTHREADS
    }
    __syncthreads();

    // ---- Phase A: chunk-local end sums, 4 chunks/warp, 8 chains interleaved ----
    {
        float F0 = 0.f, F1 = 0.f, F2 = 0.f, F3 = 0.f;
        float B0 = 0.f, B1 = 0.f, B2 = 0.f, B3 = 0.f;
        const float* x0 = xs + (w          ) * CL;
        const float* x1 = xs + (w + NWARP  ) * CL;
        const float* x2 = xs + (w + 2*NWARP) * CL;
        const float* x3 = xs + (w + 3*NWARP) * CL;
        #pragma unroll
        for (int k = 0; k < CL; k++) {
            const int kr = CL - 1 - k;
            F0 = fmaf(r, F0, x0[k]);  B0 = fmaf(r, B0, x0[kr]);
            F1 = fmaf(r, F1, x1[k]);  B1 = fmaf(r, B1, x1[kr]);
            F2 = fmaf(r, F2, x2[k]);  B2 = fmaf(r, B2, x2[kr]);
            F3 = fmaf(r, F3, x3[k]);  B3 = fmaf(r, B3, x3[kr]);
        }
        ef[w          ][lane] = F0;  eb[w          ][lane] = B0;
        ef[w + NWARP  ][lane] = F1;  eb[w + NWARP  ][lane] = B1;
        ef[w + 2*NWARP][lane] = F2;  eb[w + 2*NWARP][lane] = B2;
        ef[w + 3*NWARP][lane] = F3;  eb[w + 3*NWARP][lane] = B3;
    }
    __syncthreads();

    // ---- Phase B: inter-chunk carry propagation (hop factor r^CL) ----
    if (w == 0) {
        float T = 0.0f;
        #pragma unroll
        for (int j = 0; j < NCHUNK; j++) {
            sf[j][lane] = T;                  // seed for chunk j = S_f at j*CL-1
            T = fmaf(rL, T, ef[j][lane]);
        }
    } else if (w == 1) {
        float U = 0.0f;
        #pragma unroll
        for (int j = NCHUNK - 1; j >= 0; j--) {
            sb[j][lane] = U;                  // seed for chunk j = S_b at (j+1)*CL
            U = fmaf(rL, U, eb[j][lane]);
        }
    }
    __syncthreads();

    // ---- Phase C: seeded scans + fused combine/store for this block's quarter ----
    const int j = quar * NWARP + w;           // one chunk per warp
    const float* xc = xs + j * CL;
    float* op = out + ((size_t)b * NG + (size_t)j * CL) * NCH + lane;

    float F = sf[j][lane];
    float Freg[CL];
    #pragma unroll
    for (int k = 0; k < CL; k++) {
        F = fmaf(r, F, xc[k]);
        Freg[k] = F;
    }

    float B = sb[j][lane];
    #pragma unroll
    for (int k = CL - 1; k >= 0; k--) {
        const float xv = xc[k];
        B = fmaf(r, B, xv);
        op[(size_t)k * NCH] = scale * (Freg[k] + B - xv);
    }
}

extern "C" void kernel_launch(void* const* d_in, const int* in_sizes, int n_in,
                              void* d_out, int out_size)
{
    const float* x   = (const float*)d_in[0];  // inputs (32, 2048)
    // d_in[1] = grids (unused: uniform grid with spacing DX by construction)
    const float* eta = (const float*)d_in[2];  // eta (32,)
    float* out = (float*)d_out;                // (32, 2048, 32) fp32

    egc_scan_kernel<<<NB * BLKS_PER_B, NTHREADS>>>(x, eta, out);
}

// round 3
// speedup vs baseline: 1.2007x; 1.0717x over previous
#include <cuda_runtime.h>

// ExponentialGlobalConv: out[b,m,c] = DX * sum_n x[b,n] * exp(-|n-m|*DX/w_c) / (2 w_c)
// Uniform grid => separable exponential kernel => forward+backward IIR scan:
//   S_f[m] = x[m] + r*S_f[m-1], S_b[m] = x[m] + r*S_b[m+1], r = exp(-DX/w)
//   out[m] = scale*(S_f[m] + S_b[m] - x[m]),   scale = DX/(2w)
//
// R3: (a) all smem reads are float4 (LDS.128), (b) each block processes only a
// 64-chunk window = 16 output chunks + 24 halo chunks/side (zero-padded at row
// edges). Halo truncation error <= exp(-768*DX/w_max) = 4.6e-6 << 1e-3.

#define NCH   32
#define NG    2048
#define NB    32
#define DXC   0.08f
#define CL    32                  // chunk length
#define HALO  24                  // halo chunks per side
#define OUTC  16                  // output chunks per block
#define WINC  (OUTC + 2*HALO)     // 64 window chunks
#define NSCAN (OUTC + HALO)       // 40 chunk-scans per direction
#define NWARP 16
#define NTHREADS (NWARP * 32)
#define BPB   4                   // blocks per batch row

__global__ __launch_bounds__(NTHREADS, 1)
void egc_scan_kernel(const float* __restrict__ x,
                     const float* __restrict__ eta,
                     float* __restrict__ out)
{
    __shared__ float xs[WINC * CL];      // 2048 floats: this block's window
    __shared__ float ef[NSCAN][32];      // fwd end-sums, window chunks 0..39
    __shared__ float eb[NSCAN][32];      // bwd end-sums, window chunks 24..63 (idx-24)
    __shared__ float sf[NSCAN][32];      // fwd seeds (window chunk j)
    __shared__ float sb[NSCAN][32];      // bwd seeds (window chunk 24+i)

    const int tid  = threadIdx.x;
    const int lane = tid & 31;           // channel
    const int w    = tid >> 5;           // warp 0..15
    const int b    = blockIdx.x >> 2;    // batch row
    const int q    = blockIdx.x & 3;     // quarter of the grid dim
    const int w0c  = q * OUTC - HALO;    // window start chunk (may be <0)

    // ---- Load window (zero-padded OOB), one float4 per thread ----
    {
        const float4* xrow = reinterpret_cast<const float4*>(x + (size_t)b * NG);
        const int g4 = w0c * (CL / 4) + tid;         // global float4 index
        float4 v = make_float4(0.f, 0.f, 0.f, 0.f);
        if (g4 >= 0 && g4 < NG / 4) v = xrow[g4];
        reinterpret_cast<float4*>(xs)[tid] = v;
    }

    // ---- Per-channel params (overlap MUFU with the load) ----
    const float e     = eta[lane];
    const float sig   = 1.0f / (1.0f + __expf(-e) * 0.0f + expf(-e));  // keep exact expf
    const float wid   = 0.1f + 4.9f * sig;
    const float r     = expf(-DXC / wid);
    const float rL    = expf(-DXC * (float)CL / wid);  // r^CL, accurate
    const float scale = DXC / (2.0f * wid);

    __syncthreads();

    // ---- Phase A: chunk-local end sums, 5 chunks per warp, float4 reads ----
    if (w < 8) {
        // forward: window chunks j0..j0+4
        const int j0 = w * 5;
        float F[5];
        #pragma unroll
        for (int i = 0; i < 5; i++) F[i] = 0.f;
        #pragma unroll
        for (int g = 0; g < CL / 4; g++) {
            float4 a[5];
            #pragma unroll
            for (int i = 0; i < 5; i++)
                a[i] = *reinterpret_cast<const float4*>(xs + (j0 + i) * CL + g * 4);
            #pragma unroll
            for (int i = 0; i < 5; i++) {
                F[i] = fmaf(r, F[i], a[i].x);
                F[i] = fmaf(r, F[i], a[i].y);
                F[i] = fmaf(r, F[i], a[i].z);
                F[i] = fmaf(r, F[i], a[i].w);
            }
        }
        #pragma unroll
        for (int i = 0; i < 5; i++) ef[j0 + i][lane] = F[i];
    } else {
        // backward: window chunks (HALO + i0) .. +4, scan right-to-left
        const int i0 = (w - 8) * 5;
        float B[5];
        #pragma unroll
        for (int i = 0; i < 5; i++) B[i] = 0.f;
        #pragma unroll
        for (int g = CL / 4 - 1; g >= 0; g--) {
            float4 a[5];
            #pragma unroll
            for (int i = 0; i < 5; i++)
                a[i] = *reinterpret_cast<const float4*>(xs + (HALO + i0 + i) * CL + g * 4);
            #pragma unroll
            for (int i = 0; i < 5; i++) {
                B[i] = fmaf(r, B[i], a[i].w);
                B[i] = fmaf(r, B[i], a[i].z);
                B[i] = fmaf(r, B[i], a[i].y);
                B[i] = fmaf(r, B[i], a[i].x);
            }
        }
        #pragma unroll
        for (int i = 0; i < 5; i++) eb[i0 + i][lane] = B[i];
    }
    __syncthreads();

    // ---- Phase B: serial carry propagation with hop factor r^CL ----
    if (w == 0) {
        float T = 0.0f;
        #pragma unroll
        for (int j = 0; j < NSCAN; j++) {
            sf[j][lane] = T;                   // seed for window chunk j
            T = fmaf(rL, T, ef[j][lane]);
        }
    } else if (w == 1) {
        float U = 0.0f;
        #pragma unroll
        for (int i = NSCAN - 1; i >= 0; i--) {
            sb[i][lane] = U;                   // seed for window chunk HALO+i
            U = fmaf(rL, U, eb[i][lane]);
        }
    }
    __syncthreads();

    // ---- Phase C: seeded scans + fused combine/store, 1 out-chunk per warp ----
    const int jo = HALO + w;                   // window chunk
    const float* xc = xs + jo * CL;
    float* op = out + ((size_t)b * NG + (size_t)(q * OUTC + w) * CL) * NCH + lane;

    float xr[CL];
    #pragma unroll
    for (int g = 0; g < CL / 4; g++) {
        float4 a = *reinterpret_cast<const float4*>(xc + g * 4);
        xr[g * 4 + 0] = a.x; xr[g * 4 + 1] = a.y;
        xr[g * 4 + 2] = a.z; xr[g * 4 + 3] = a.w;
    }

    float F = sf[jo][lane];
    float Freg[CL];
    #pragma unroll
    for (int k = 0; k < CL; k++) {
        F = fmaf(r, F, xr[k]);
        Freg[k] = F;
    }

    float B = sb[w][lane];
    #pragma unroll
    for (int k = CL - 1; k >= 0; k--) {
        B = fmaf(r, B, xr[k]);
        op[(size_t)k * NCH] = scale * (Freg[k] + B - xr[k]);
    }
}

extern "C" void kernel_launch(void* const* d_in, const int* in_sizes, int n_in,
                              void* d_out, int out_size)
{
    const float* x   = (const float*)d_in[0];  // inputs (32, 2048)
    // d_in[1] = grids (unused: uniform grid, spacing DX by construction)
    const float* eta = (const float*)d_in[2];  // eta (32,)
    float* out = (float*)d_out;                // (32, 2048, 32) fp32

    egc_scan_kernel<<<NB * BPB, NTHREADS>>>(x, eta, out);
}